// round 8
// baseline (speedup 1.0000x reference)
#include <cuda_runtime.h>
#include <cstdint>

// Problem shape (fixed for this dataset entry)
#define B_    2
#define N_    50000
#define C_    64
#define M_    50000
#define K_    16
#define H_    8
#define CMID_ 16
#define PPC   8    // points per CTA (one warp each)

// Runtime-detected index width flag (int64 vs int32), set by detect kernel.
__device__ int g_idx_is64;

__global__ void detect_idx_kernel(const unsigned int* __restrict__ w) {
    if (threadIdx.x == 0 && blockIdx.x == 0) {
        int is64 = 1;
        #pragma unroll 1
        for (int i = 0; i < 256; i++) {
            if (w[2 * i + 1] != 0u) { is64 = 0; break; }
        }
        g_idx_is64 = is64;
    }
}

// One WARP per point; 8 points per 256-thread CTA; no CTA-wide syncs.
//
// Stage (per warp, zero-duplication LDG only):
//   guid 512B: 1 LDG.128 pass -> smem.      wn 1KB: 2 LDG.128 passes -> smem.
//   feat: 8 LDG.128 passes (512B each, lanes cover rows exactly once),
//         guidance scale applied in-flight (2 mul.rn.f32x2), STS.128.
//   => guidance is eliminated from the k-loop entirely.
//
// Compute (R7's minimal tile: cg=lane&7 owns 8 contiguous channels,
// jq=lane>>3 owns 4 w):
//   per k: 2 LDS.128 feat (4-dup -> crossbar broadcast, conflict-free)
//        + 1 LDS.128 W (uniform -> broadcast) + 4 dup movs + 16 fma.rn.f32x2.
//   Multiplier channel-pairs arrive packed AND pre-scaled from the feat LDS.
//   acc[i*4+j] = {out[8cg+2i][4jq+j], out[8cg+2i+1][4jq+j]}.
__global__ void __launch_bounds__(256, 5)
pcf_kernel(const float* __restrict__ feat,
           const void*  __restrict__ inds_raw,
           const float* __restrict__ guid,
           const float* __restrict__ wn,
           float* __restrict__ out)
{
    __shared__ __align__(16) float sft[PPC][K_ * C_];    // 8 x 4KB scaled gathered feat
    __shared__ __align__(16) float swn[PPC][K_ * CMID_]; // 8 x 1KB  weightnet
    __shared__ __align__(16) float sgd[PPC][K_ * H_];    // 8 x 512B guidance
    __shared__ int sidx[PPC][K_];

    const int wid  = threadIdx.x >> 5;
    const int lane = threadIdx.x & 31;
    const int p    = blockIdx.x * PPC + wid;    // point id in [0, B*M)
    const int b    = (p >= M_) ? 1 : 0;
    const int cg   = lane & 7;                  // channel group: ch [8cg, 8cg+8)
    const int jq   = lane >> 3;                 // w quad [4jq, 4jq+4)

    // ---- stage wn (1KB), guid (512B), indices ----
    {
        const float4* wsrc = (const float4*)(wn + (size_t)p * (K_ * CMID_));
        float4* wdst = (float4*)(swn[wid]);
        wdst[lane]      = wsrc[lane];
        wdst[lane + 32] = wsrc[lane + 32];
        ((float4*)(sgd[wid]))[lane] = ((const float4*)(guid + (size_t)p * (K_ * H_)))[lane];
        if (lane < K_) {
            long long idx;
            if (g_idx_is64) idx = ((const long long*)inds_raw)[(size_t)p * K_ + lane];
            else            idx = (long long)((const int*)inds_raw)[(size_t)p * K_ + lane];
            sidx[wid][lane] = (int)idx;
        }
    }
    __syncwarp();

    // ---- stage gathered features, guidance fused (zero-dup LDG.128 x8) ----
    {
        const float* fb = feat + (size_t)b * ((size_t)N_ * C_);
        #pragma unroll
        for (int j = 0; j < 8; j++) {
            const int li = j * 32 + lane;       // 0..255
            const int r  = li >> 4;             // neighbor row 0..15
            const int ch = li & 15;             // 16B chunk: channels 4ch..4ch+3
            const float4 v = *(const float4*)(fb + (size_t)sidx[wid][r] * C_ + ch * 4);
            const float  s = sgd[wid][r * H_ + (ch >> 1)];  // head = 4ch/8
            *(float4*)(sft[wid] + r * C_ + ch * 4) =
                make_float4(v.x * s, v.y * s, v.z * s, v.w * s);
        }
    }
    __syncwarp();

    // ---- compute: all operands from broadcast-friendly LDS ----
    unsigned long long acc[16];
    #pragma unroll
    for (int i = 0; i < 16; i++) acc[i] = 0ull;

    #pragma unroll 4
    for (int k = 0; k < K_; k++) {
        // this lane's 8 pre-scaled channels, packed as 4 c-pairs
        const ulonglong2* frow = (const ulonglong2*)(sft[wid] + k * C_ + 8 * cg);
        const ulonglong2 f0 = frow[0];   // {ch0,ch1},{ch2,ch3}
        const ulonglong2 f1 = frow[1];   // {ch4,ch5},{ch6,ch7}

        // this lane's 4 W values: ONE uniform LDS.128
        const float4 W = *(const float4*)(swn[wid] + k * CMID_ + 4 * jq);
        unsigned long long w0, w1, w2, w3;
        asm("mov.b64 %0, {%1, %1};" : "=l"(w0) : "f"(W.x));
        asm("mov.b64 %0, {%1, %1};" : "=l"(w1) : "f"(W.y));
        asm("mov.b64 %0, {%1, %1};" : "=l"(w2) : "f"(W.z));
        asm("mov.b64 %0, {%1, %1};" : "=l"(w3) : "f"(W.w));

        asm("fma.rn.f32x2 %0, %1, %2, %3;" : "=l"(acc[ 0]) : "l"(f0.x), "l"(w0), "l"(acc[ 0]));
        asm("fma.rn.f32x2 %0, %1, %2, %3;" : "=l"(acc[ 1]) : "l"(f0.x), "l"(w1), "l"(acc[ 1]));
        asm("fma.rn.f32x2 %0, %1, %2, %3;" : "=l"(acc[ 2]) : "l"(f0.x), "l"(w2), "l"(acc[ 2]));
        asm("fma.rn.f32x2 %0, %1, %2, %3;" : "=l"(acc[ 3]) : "l"(f0.x), "l"(w3), "l"(acc[ 3]));
        asm("fma.rn.f32x2 %0, %1, %2, %3;" : "=l"(acc[ 4]) : "l"(f0.y), "l"(w0), "l"(acc[ 4]));
        asm("fma.rn.f32x2 %0, %1, %2, %3;" : "=l"(acc[ 5]) : "l"(f0.y), "l"(w1), "l"(acc[ 5]));
        asm("fma.rn.f32x2 %0, %1, %2, %3;" : "=l"(acc[ 6]) : "l"(f0.y), "l"(w2), "l"(acc[ 6]));
        asm("fma.rn.f32x2 %0, %1, %2, %3;" : "=l"(acc[ 7]) : "l"(f0.y), "l"(w3), "l"(acc[ 7]));
        asm("fma.rn.f32x2 %0, %1, %2, %3;" : "=l"(acc[ 8]) : "l"(f1.x), "l"(w0), "l"(acc[ 8]));
        asm("fma.rn.f32x2 %0, %1, %2, %3;" : "=l"(acc[ 9]) : "l"(f1.x), "l"(w1), "l"(acc[ 9]));
        asm("fma.rn.f32x2 %0, %1, %2, %3;" : "=l"(acc[10]) : "l"(f1.x), "l"(w2), "l"(acc[10]));
        asm("fma.rn.f32x2 %0, %1, %2, %3;" : "=l"(acc[11]) : "l"(f1.x), "l"(w3), "l"(acc[11]));
        asm("fma.rn.f32x2 %0, %1, %2, %3;" : "=l"(acc[12]) : "l"(f1.y), "l"(w0), "l"(acc[12]));
        asm("fma.rn.f32x2 %0, %1, %2, %3;" : "=l"(acc[13]) : "l"(f1.y), "l"(w1), "l"(acc[13]));
        asm("fma.rn.f32x2 %0, %1, %2, %3;" : "=l"(acc[14]) : "l"(f1.y), "l"(w2), "l"(acc[14]));
        asm("fma.rn.f32x2 %0, %1, %2, %3;" : "=l"(acc[15]) : "l"(f1.y), "l"(w3), "l"(acc[15]));
    }

    // ---- epilogue: acc[i*4+j].lo -> row 8cg+2i, .hi -> row 8cg+2i+1, col 4jq+j
    float* o = out + (size_t)p * (C_ * CMID_) + (size_t)(8 * cg) * CMID_ + 4 * jq;
    #pragma unroll
    for (int i = 0; i < 4; i++) {
        float2 v0 = *(float2*)&acc[i * 4 + 0];
        float2 v1 = *(float2*)&acc[i * 4 + 1];
        float2 v2 = *(float2*)&acc[i * 4 + 2];
        float2 v3 = *(float2*)&acc[i * 4 + 3];
        *(float4*)(o + (2 * i) * CMID_)     = make_float4(v0.x, v1.x, v2.x, v3.x);
        *(float4*)(o + (2 * i + 1) * CMID_) = make_float4(v0.y, v1.y, v2.y, v3.y);
    }
}

extern "C" void kernel_launch(void* const* d_in, const int* in_sizes, int n_in,
                              void* d_out, int out_size) {
    const float* feat = (const float*)d_in[0];
    const void*  inds = d_in[1];
    const float* guid = (const float*)d_in[2];
    const float* wn   = (const float*)d_in[3];
    float* out = (float*)d_out;

    detect_idx_kernel<<<1, 32>>>((const unsigned int*)inds);
    pcf_kernel<<<(B_ * M_) / PPC, 256>>>(feat, inds, guid, wn, out);
}

// round 12
// speedup vs baseline: 2.2445x; 2.2445x over previous
#include <cuda_runtime.h>
#include <cstdint>

// Problem shape (fixed for this dataset entry)
#define B_    2
#define N_    50000
#define C_    64
#define M_    50000
#define K_    16
#define H_    8
#define CMID_ 16
#define PF    4    // gather prefetch depth

// Runtime-detected index width flag (int64 vs int32), set by detect kernel.
__device__ int g_idx_is64;

__global__ void detect_idx_kernel(const unsigned int* __restrict__ w) {
    if (threadIdx.x == 0 && blockIdx.x == 0) {
        int is64 = 1;
        #pragma unroll 1
        for (int i = 0; i < 256; i++) {
            if (w[2 * i + 1] != 0u) { is64 = 0; break; }
        }
        g_idx_is64 = is64;
    }
}

// One WARP per point; 4 points per 128-thread CTA.
// Compute stage identical to the 191us R3 kernel (best so far):
//   lane l owns channels {2l, 2l+1} and all 16 w; zero-dup LDG.64 gather,
//   4 uniform LDS.128 per k for W, scalar guid LDS, 16 fma.rn.f32x2 per k.
// CHANGED (one variable): the epilogue. R3 stored with lane-stride 128B
//   => 32 lines per STG.128 instruction (8 x 32 = 256 L1 wavefronts/point,
//   tied-largest L1 term). Now: accumulators -> smem (8 STS.128, chunk i at
//   swizzled slot (i+lane)&7 -> conflict-free) -> remapped read (8 LDS.128,
//   conflict-free) -> 8 fully-coalesced STG.128 (512B contiguous, 4 lines).
// (R11 bug fixed: store chunk i's DATA acc[2i],acc[2i+1] at slot ip; R11
//  stored acc[2*ip] which degenerated to identity placement.)
__global__ void __launch_bounds__(128)
pcf_kernel(const float* __restrict__ feat,
           const void*  __restrict__ inds_raw,
           const float* __restrict__ guid,
           const float* __restrict__ wn,
           float* __restrict__ out)
{
    __shared__ __align__(16) float swn[4][K_ * CMID_];  // 4 x 1KB  weightnet
    __shared__ __align__(16) float sgd[4][K_ * H_];     // 4 x 512B guidance
    __shared__ __align__(16) float sout[4][1024];       // 4 x 4KB  output bounce
    __shared__ int sidx[4][K_];

    const int wid  = threadIdx.x >> 5;
    const int lane = threadIdx.x & 31;
    const int p    = blockIdx.x * 4 + wid;      // point id in [0, B*M)
    const int b    = (p >= M_) ? 1 : 0;
    const int hd   = lane >> 2;                 // head of channels {2l,2l+1}

    // ---- per-warp staging: weightnet (1KB), guidance (512B), indices ----
    {
        const float4* wsrc = (const float4*)(wn + (size_t)p * (K_ * CMID_));
        float4* wdst = (float4*)(swn[wid]);
        wdst[lane]      = wsrc[lane];
        wdst[lane + 32] = wsrc[lane + 32];
        ((float4*)(sgd[wid]))[lane] = ((const float4*)(guid + (size_t)p * (K_ * H_)))[lane];
        if (lane < K_) {
            long long idx;
            if (g_idx_is64) idx = ((const long long*)inds_raw)[(size_t)p * K_ + lane];
            else            idx = (long long)((const int*)inds_raw)[(size_t)p * K_ + lane];
            sidx[wid][lane] = (int)idx;
        }
    }
    __syncwarp();

    // lane-fixed channel offset: feature row base + channel 2*lane
    const float* fb = feat + (size_t)b * ((size_t)N_ * C_) + 2 * lane;

    // ---- prefetch pipeline for the gather (zero-dup LDG.64) ----
    float2 gbuf[PF];
    #pragma unroll
    for (int i = 0; i < PF; i++)
        gbuf[i] = *(const float2*)(fb + (size_t)sidx[wid][i] * C_);

    unsigned long long acc[16];
    #pragma unroll
    for (int i = 0; i < 16; i++) acc[i] = 0ull;

    #pragma unroll
    for (int k = 0; k < K_; k++) {
        float2 f = gbuf[k % PF];
        if (k + PF < K_)
            gbuf[k % PF] = *(const float2*)(fb + (size_t)sidx[wid][k + PF] * C_);

        const float g = sgd[wid][k * H_ + hd];  // broadcast (8 distinct words)
        const float s0 = f.x * g;
        const float s1 = f.y * g;
        unsigned long long g0, g1;
        asm("mov.b64 %0, {%1, %1};" : "=l"(g0) : "f"(s0));
        asm("mov.b64 %0, {%1, %1};" : "=l"(g1) : "f"(s1));

        // W row k: 16 floats = 4 uniform LDS.128 -> 8 packed {w2j, w2j+1}
        const ulonglong2* wr = (const ulonglong2*)(swn[wid] + k * CMID_);
        ulonglong2 A = wr[0];   // {w0w1, w2w3}
        ulonglong2 Bv = wr[1];  // {w4w5, w6w7}
        ulonglong2 Cv = wr[2];  // {w8w9, w10w11}
        ulonglong2 Dv = wr[3];  // {w12w13, w14w15}

        asm("fma.rn.f32x2 %0, %1, %2, %3;" : "=l"(acc[ 0]) : "l"(g0), "l"(A.x),  "l"(acc[ 0]));
        asm("fma.rn.f32x2 %0, %1, %2, %3;" : "=l"(acc[ 1]) : "l"(g0), "l"(A.y),  "l"(acc[ 1]));
        asm("fma.rn.f32x2 %0, %1, %2, %3;" : "=l"(acc[ 2]) : "l"(g0), "l"(Bv.x), "l"(acc[ 2]));
        asm("fma.rn.f32x2 %0, %1, %2, %3;" : "=l"(acc[ 3]) : "l"(g0), "l"(Bv.y), "l"(acc[ 3]));
        asm("fma.rn.f32x2 %0, %1, %2, %3;" : "=l"(acc[ 4]) : "l"(g0), "l"(Cv.x), "l"(acc[ 4]));
        asm("fma.rn.f32x2 %0, %1, %2, %3;" : "=l"(acc[ 5]) : "l"(g0), "l"(Cv.y), "l"(acc[ 5]));
        asm("fma.rn.f32x2 %0, %1, %2, %3;" : "=l"(acc[ 6]) : "l"(g0), "l"(Dv.x), "l"(acc[ 6]));
        asm("fma.rn.f32x2 %0, %1, %2, %3;" : "=l"(acc[ 7]) : "l"(g0), "l"(Dv.y), "l"(acc[ 7]));
        asm("fma.rn.f32x2 %0, %1, %2, %3;" : "=l"(acc[ 8]) : "l"(g1), "l"(A.x),  "l"(acc[ 8]));
        asm("fma.rn.f32x2 %0, %1, %2, %3;" : "=l"(acc[ 9]) : "l"(g1), "l"(A.y),  "l"(acc[ 9]));
        asm("fma.rn.f32x2 %0, %1, %2, %3;" : "=l"(acc[10]) : "l"(g1), "l"(Bv.x), "l"(acc[10]));
        asm("fma.rn.f32x2 %0, %1, %2, %3;" : "=l"(acc[11]) : "l"(g1), "l"(Bv.y), "l"(acc[11]));
        asm("fma.rn.f32x2 %0, %1, %2, %3;" : "=l"(acc[12]) : "l"(g1), "l"(Cv.x), "l"(acc[12]));
        asm("fma.rn.f32x2 %0, %1, %2, %3;" : "=l"(acc[13]) : "l"(g1), "l"(Cv.y), "l"(acc[13]));
        asm("fma.rn.f32x2 %0, %1, %2, %3;" : "=l"(acc[14]) : "l"(g1), "l"(Dv.x), "l"(acc[14]));
        asm("fma.rn.f32x2 %0, %1, %2, %3;" : "=l"(acc[15]) : "l"(g1), "l"(Dv.y), "l"(acc[15]));
    }

    // ---- epilogue: swizzled smem bounce, then fully-coalesced STG ----
    // Lane L's 32-float flat block (row 2L = acc[0..7] -> floats 0..15,
    // row 2L+1 = acc[8..15] -> floats 16..31) lives at sout[wid] + L*32.
    // Chunk i (floats 4i..4i+3 = {acc[2i], acc[2i+1]}) is stored at swizzled
    // slot ip=(i+L)&7. Per 8-lane phase all ip distinct -> conflict-free.
    {
        float* sb = sout[wid] + lane * 32;
        #pragma unroll
        for (int i = 0; i < 8; i++) {
            const int ip = (i + lane) & 7;           // swizzled chunk slot
            *(ulonglong2*)(sb + ip * 4) =
                make_ulonglong2(acc[2 * i], acc[2 * i + 1]);
        }
    }
    __syncwarp();
    // Coalesced flush (FLOAT units): lane handles global floats
    // flat = j*128 + lane*4 .. +4. Source: lane s = flat/32, chunk
    // i = (flat%32)/4, physical slot ip = (i+s)&7. Read phase of 8 lanes
    // shares s, distinct ip -> conflict-free. STG: 512B contiguous per j.
    {
        float* o = out + (size_t)p * (C_ * CMID_);
        #pragma unroll
        for (int j = 0; j < 8; j++) {
            const int flat = j * 128 + lane * 4;     // global float index
            const int s    = flat >> 5;              // source lane (32 floats ea)
            const int i    = (flat >> 2) & 7;        // chunk within source block
            const int ip   = (i + s) & 7;            // swizzled slot
            const float4 v = *(const float4*)(sout[wid] + s * 32 + ip * 4);
            *(float4*)(o + flat) = v;
        }
    }
}

extern "C" void kernel_launch(void* const* d_in, const int* in_sizes, int n_in,
                              void* d_out, int out_size) {
    const float* feat = (const float*)d_in[0];
    const void*  inds = d_in[1];
    const float* guid = (const float*)d_in[2];
    const float* wn   = (const float*)d_in[3];
    float* out = (float*)d_out;

    detect_idx_kernel<<<1, 32>>>((const unsigned int*)inds);
    pcf_kernel<<<(B_ * M_) / 4, 128>>>(feat, inds, guid, wn, out);
}